// round 1
// baseline (speedup 1.0000x reference)
#include <cuda_runtime.h>
#include <math.h>

#define B        4096
#define IN_SIZE  512
#define OUT_SIZE 256
#define NQ       12
#define DEPTH    3
#define NSTATES  4096   // 2^NQ
#define BN_EPS   1e-5f

// ---------------- scratch (device globals; no allocation) ----------------
__device__ float g_encoded[B * NQ];
__device__ float g_bn1_sc[NQ];
__device__ float g_bn1_sh[NQ];
__device__ float g_gates[DEPTH * NQ * 8];      // 2x2 complex per gate (r,i interleaved)
__device__ float g_cry[DEPTH * (NQ - 1) * 2];  // cos, sin per CRY
__device__ float g_bn2_sc[OUT_SIZE];
__device__ float g_bn2_sh[OUT_SIZE];

// ---------------- kernel 1: encoded = x @ enc_w.T + enc_b ----------------
// one warp per row, enc_w staged in smem
__global__ void k_encode(const float* __restrict__ x,
                         const float* __restrict__ enc_w,
                         const float* __restrict__ enc_b) {
    __shared__ float w_s[NQ * IN_SIZE];  // 24KB
    int tid = threadIdx.x;
    for (int i = tid; i < NQ * IN_SIZE; i += 256) w_s[i] = enc_w[i];
    __syncthreads();

    int warp = tid >> 5, lane = tid & 31;
    int row = blockIdx.x * 8 + warp;
    const float* xr = x + row * IN_SIZE;

    float acc[NQ];
#pragma unroll
    for (int q = 0; q < NQ; ++q) acc[q] = 0.f;

    for (int k = lane; k < IN_SIZE; k += 32) {
        float xv = xr[k];
#pragma unroll
        for (int q = 0; q < NQ; ++q) acc[q] += xv * w_s[q * IN_SIZE + k];
    }
#pragma unroll
    for (int q = 0; q < NQ; ++q) {
#pragma unroll
        for (int o = 16; o > 0; o >>= 1)
            acc[q] += __shfl_xor_sync(0xffffffffu, acc[q], o);
    }
    if (lane == 0) {
#pragma unroll
        for (int q = 0; q < NQ; ++q)
            g_encoded[row * NQ + q] = acc[q] + enc_b[q];
    }
}

// ---------------- kernel 2: BN1 stats + gate matrix precompute ----------------
struct C2 { float r, i; };
__device__ __forceinline__ C2 cmul(C2 a, C2 b) {
    C2 c; c.r = a.r * b.r - a.i * b.i; c.i = a.r * b.i + a.i * b.r; return c;
}
__device__ __forceinline__ C2 cadd(C2 a, C2 b) { C2 c; c.r = a.r + b.r; c.i = a.i + b.i; return c; }
__device__ void mm2(const C2* A, const C2* Bm, C2* O) {
    O[0] = cadd(cmul(A[0], Bm[0]), cmul(A[1], Bm[2]));
    O[1] = cadd(cmul(A[0], Bm[1]), cmul(A[1], Bm[3]));
    O[2] = cadd(cmul(A[2], Bm[0]), cmul(A[3], Bm[2]));
    O[3] = cadd(cmul(A[2], Bm[1]), cmul(A[3], Bm[3]));
}

__global__ void k_prep(const float* __restrict__ rot_params,
                       const float* __restrict__ ent_params,
                       const float* __restrict__ bn1_gamma,
                       const float* __restrict__ bn1_beta) {
    int tid = threadIdx.x;
    if (blockIdx.x < NQ) {
        // per-feature mean/var over 4096 rows
        int f = blockIdx.x;
        float s = 0.f, s2 = 0.f;
        for (int r = tid; r < B; r += 256) {
            float v = g_encoded[r * NQ + f];
            s += v; s2 += v * v;
        }
#pragma unroll
        for (int o = 16; o > 0; o >>= 1) {
            s  += __shfl_xor_sync(0xffffffffu, s, o);
            s2 += __shfl_xor_sync(0xffffffffu, s2, o);
        }
        __shared__ float rs[8], rs2[8];
        int w = tid >> 5, lane = tid & 31;
        if (lane == 0) { rs[w] = s; rs2[w] = s2; }
        __syncthreads();
        if (tid == 0) {
            float S = 0.f, S2 = 0.f;
            for (int i = 0; i < 8; ++i) { S += rs[i]; S2 += rs2[i]; }
            float mean = S / (float)B;
            float var = S2 / (float)B - mean * mean;
            float sc = bn1_gamma[f] * rsqrtf(var + BN_EPS);
            g_bn1_sc[f] = sc;
            g_bn1_sh[f] = bn1_beta[f] - mean * sc;
        }
    } else {
        // gate matrices
        if (tid < DEPTH * NQ) {
            int l = tid / NQ, q = tid % NQ;
            float a = rot_params[(l * NQ + q) * 3 + 0];
            float b = rot_params[(l * NQ + q) * 3 + 1];
            float g = rot_params[(l * NQ + q) * 3 + 2];
            float cx = cosf(0.5f * a), sx = sinf(0.5f * a);
            float cy = cosf(0.5f * b), sy = sinf(0.5f * b);
            float cg = cosf(0.5f * g), sg = sinf(0.5f * g);
            C2 Rx[4] = { {cx,0.f},{0.f,-sx},{0.f,-sx},{cx,0.f} };
            C2 Ry[4] = { {cy,0.f},{-sy,0.f},{sy,0.f},{cy,0.f} };
            C2 Rz[4] = { {cg,-sg},{0.f,0.f},{0.f,0.f},{cg,sg} };
            C2 T[4], U[4];
            mm2(Ry, Rx, T);
            mm2(Rz, T, U);
            float* o = &g_gates[tid * 8];
#pragma unroll
            for (int e = 0; e < 4; ++e) { o[e * 2] = U[e].r; o[e * 2 + 1] = U[e].i; }
        }
        if (tid >= 64 && tid < 64 + DEPTH * (NQ - 1)) {
            int t = tid - 64;
            float th = ent_params[t];
            g_cry[t * 2] = cosf(0.5f * th);
            g_cry[t * 2 + 1] = sinf(0.5f * th);
        }
    }
}

// ---------------- kernel 3: main quantum simulator ----------------
// one CTA (256 threads) per sample; full statevector in SMEM
__global__ __launch_bounds__(256) void k_quantum(const float* __restrict__ dec_w,
                                                 const float* __restrict__ dec_b,
                                                 float* __restrict__ out) {
    __shared__ float2 st[NSTATES];                 // 32KB
    __shared__ float hq0[NQ], hq1[NQ];
    __shared__ float probs_s[NQ];
    __shared__ float wsum[8][NQ];

    int tid = threadIdx.x;
    int sample = blockIdx.x;

    // BN1 + tanh
    if (tid < NQ) {
        float e = g_encoded[sample * NQ + tid];
        hq0[tid] = tanhf(g_bn1_sc[tid] * e + g_bn1_sh[tid]);
    }
    __syncthreads();
    if (tid == 0) {
        float ss = 0.f;
#pragma unroll
        for (int q = 0; q < NQ; ++q) ss += hq0[q] * hq0[q];
        float nrm = sqrtf(ss);
#pragma unroll
        for (int q = 0; q < NQ; ++q) {
            float h = hq0[q];
            float a = (nrm > 0.f) ? h / fmaxf(nrm, 1e-30f) : h;
            float amp = fminf(fabsf(a), 1.0f);
            float ch = sqrtf(fmaxf(1.0f - amp * amp, 0.0f));
            hq0[q] = ch;
            hq1[q] = (a < 0.f) ? -amp : amp;
        }
    }
    __syncthreads();

    // initial product state (real)
    for (int i = tid; i < NSTATES; i += 256) {
        float v = 1.f;
#pragma unroll
        for (int q = 0; q < NQ; ++q)
            v *= ((i >> (11 - q)) & 1) ? hq1[q] : hq0[q];
        st[i] = make_float2(v, 0.f);
    }
    __syncthreads();

    // layers
    for (int l = 0; l < DEPTH; ++l) {
        for (int q = 0; q < NQ; ++q) {
            const float* u = &g_gates[(l * NQ + q) * 8];
            float u00r = u[0], u00i = u[1], u01r = u[2], u01i = u[3];
            float u10r = u[4], u10i = u[5], u11r = u[6], u11i = u[7];
            int m = 11 - q;
            int s = 1 << m;
            for (int p = tid; p < NSTATES / 2; p += 256) {
                int low = p & (s - 1);
                int i0 = ((p - low) << 1) | low;
                int i1 = i0 + s;
                float2 a = st[i0], b = st[i1];
                float2 na, nb;
                na.x = u00r * a.x - u00i * a.y + u01r * b.x - u01i * b.y;
                na.y = u00r * a.y + u00i * a.x + u01r * b.y + u01i * b.x;
                nb.x = u10r * a.x - u10i * a.y + u11r * b.x - u11i * b.y;
                nb.y = u10r * a.y + u10i * a.x + u11r * b.y + u11i * b.x;
                st[i0] = na; st[i1] = nb;
            }
            __syncthreads();
        }
        for (int j = 0; j < NQ - 1; ++j) {
            float c  = g_cry[(l * (NQ - 1) + j) * 2];
            float sn = g_cry[(l * (NQ - 1) + j) * 2 + 1];
            int mt = 10 - j;               // target bit
            int lowmask = (1 << mt) - 1;
            for (int p = tid; p < NSTATES / 4; p += 256) {
                int low = p & lowmask;
                int i0 = ((p - low) << 2) | (1 << (mt + 1)) | low;  // control bit = 1, target = 0
                int i1 = i0 | (1 << mt);
                float2 a = st[i0], b = st[i1];
                float2 na, nb;
                na.x = c * a.x - sn * b.x;  na.y = c * a.y - sn * b.y;
                nb.x = sn * a.x + c * b.x;  nb.y = sn * a.y + c * b.y;
                st[i0] = na; st[i1] = nb;
            }
            __syncthreads();
        }
    }

    // probs[q] = sum_{i: bit(11-q)=1} |amp_i|^2
    float acc[NQ];
#pragma unroll
    for (int q = 0; q < NQ; ++q) acc[q] = 0.f;
    for (int i = tid; i < NSTATES; i += 256) {
        float2 a = st[i];
        float p2 = a.x * a.x + a.y * a.y;
#pragma unroll
        for (int q = 0; q < NQ; ++q)
            if ((i >> (11 - q)) & 1) acc[q] += p2;
    }
#pragma unroll
    for (int q = 0; q < NQ; ++q) {
#pragma unroll
        for (int o = 16; o > 0; o >>= 1)
            acc[q] += __shfl_xor_sync(0xffffffffu, acc[q], o);
    }
    int w = tid >> 5, lane = tid & 31;
    if (lane == 0) {
#pragma unroll
        for (int q = 0; q < NQ; ++q) wsum[w][q] = acc[q];
    }
    __syncthreads();
    if (tid < NQ) {
        float s = 0.f;
#pragma unroll
        for (int ww = 0; ww < 8; ++ww) s += wsum[ww][tid];
        probs_s[tid] = s;
    }
    __syncthreads();

    // decode: out[f] = probs . dec_w[f,:] + dec_b[f]  (pre-BN2)
    {
        float o = dec_b[tid];
#pragma unroll
        for (int q = 0; q < NQ; ++q) o += probs_s[q] * dec_w[tid * NQ + q];
        out[sample * OUT_SIZE + tid] = o;
    }
}

// ---------------- kernel 4: BN2 stats ----------------
__global__ void k_bn2_stats(const float* __restrict__ out,
                            const float* __restrict__ bn2_gamma,
                            const float* __restrict__ bn2_beta) {
    int f = blockIdx.x;
    int tid = threadIdx.x;
    float s = 0.f, s2 = 0.f;
    for (int r = tid; r < B; r += 256) {
        float v = out[r * OUT_SIZE + f];
        s += v; s2 += v * v;
    }
#pragma unroll
    for (int o = 16; o > 0; o >>= 1) {
        s  += __shfl_xor_sync(0xffffffffu, s, o);
        s2 += __shfl_xor_sync(0xffffffffu, s2, o);
    }
    __shared__ float rs[8], rs2[8];
    int w = tid >> 5, lane = tid & 31;
    if (lane == 0) { rs[w] = s; rs2[w] = s2; }
    __syncthreads();
    if (tid == 0) {
        float S = 0.f, S2 = 0.f;
        for (int i = 0; i < 8; ++i) { S += rs[i]; S2 += rs2[i]; }
        float mean = S / (float)B;
        float var = S2 / (float)B - mean * mean;
        float sc = bn2_gamma[f] * rsqrtf(var + BN_EPS);
        g_bn2_sc[f] = sc;
        g_bn2_sh[f] = bn2_beta[f] - mean * sc;
    }
}

// ---------------- kernel 5: BN2 apply ----------------
__global__ void k_bn2_apply(float* __restrict__ out) {
    int i = blockIdx.x * 256 + threadIdx.x;
    int f = i & (OUT_SIZE - 1);
    out[i] = g_bn2_sc[f] * out[i] + g_bn2_sh[f];
}

// ---------------- launcher ----------------
extern "C" void kernel_launch(void* const* d_in, const int* in_sizes, int n_in,
                              void* d_out, int out_size) {
    const float* x          = (const float*)d_in[0];
    const float* enc_w      = (const float*)d_in[1];
    const float* enc_b      = (const float*)d_in[2];
    const float* rot_params = (const float*)d_in[3];
    const float* ent_params = (const float*)d_in[4];
    const float* dec_w      = (const float*)d_in[5];
    const float* dec_b      = (const float*)d_in[6];
    const float* bn1_gamma  = (const float*)d_in[7];
    const float* bn1_beta   = (const float*)d_in[8];
    const float* bn2_gamma  = (const float*)d_in[9];
    const float* bn2_beta   = (const float*)d_in[10];
    float* out = (float*)d_out;

    k_encode<<<B / 8, 256>>>(x, enc_w, enc_b);
    k_prep<<<NQ + 1, 256>>>(rot_params, ent_params, bn1_gamma, bn1_beta);
    k_quantum<<<B, 256>>>(dec_w, dec_b, out);
    k_bn2_stats<<<OUT_SIZE, 256>>>(out, bn2_gamma, bn2_beta);
    k_bn2_apply<<<(B * OUT_SIZE) / 256, 256>>>(out);
}

// round 5
// speedup vs baseline: 1.9487x; 1.9487x over previous
#include <cuda_runtime.h>
#include <math.h>

#define B        4096
#define IN_SIZE  512
#define OUT_SIZE 256
#define NQ       12
#define DEPTH    3
#define NSTATES  4096
#define BN_EPS   1e-5f

typedef unsigned long long ull;

// ---------------- scratch (device globals; no allocation) ----------------
__device__ float g_encoded[B * NQ];
__device__ float g_bn1_sc[NQ];
__device__ float g_bn1_sh[NQ];
__device__ float g_gates[DEPTH * NQ * 8];      // 2x2 complex per gate
__device__ float g_cry[DEPTH * (NQ - 1) * 2];  // cos, sin per CRY
__device__ float g_bn2_sc[OUT_SIZE];
__device__ float g_bn2_sh[OUT_SIZE];
__device__ float g_p1[64 * OUT_SIZE];
__device__ float g_p2[64 * OUT_SIZE];

// ---------------- f32x2 packed helpers ----------------
__device__ __forceinline__ ull fma2(ull a, ull b, ull c) {
    ull d; asm("fma.rn.f32x2 %0,%1,%2,%3;" : "=l"(d) : "l"(a), "l"(b), "l"(c)); return d;
}
__device__ __forceinline__ ull mul2(ull a, ull b) {
    ull d; asm("mul.rn.f32x2 %0,%1,%2;" : "=l"(d) : "l"(a), "l"(b)); return d;
}
__device__ __forceinline__ ull pack2(float lo, float hi) {
    ull d; asm("mov.b64 %0,{%1,%2};" : "=l"(d) : "f"(lo), "f"(hi)); return d;
}
__device__ __forceinline__ void unpack2(ull a, float& lo, float& hi) {
    asm("mov.b64 {%0,%1},%2;" : "=f"(lo), "=f"(hi) : "l"(a));
}
__device__ __forceinline__ ull swap2(ull a) { float lo, hi; unpack2(a, lo, hi); return pack2(hi, lo); }
__device__ __forceinline__ ull splat2(float v) { return pack2(v, v); }

// complex 2x2 butterfly, SIMD-splat coefficients, A at (ar,ai), B at (br,bi)
struct CGate { ull c00r,c00in,c00ip,c01r,c01in,c01ip,c10r,c10in,c10ip,c11r,c11in,c11ip; };
__device__ __forceinline__ CGate make_cgate(const float* u) {
    CGate g;
    g.c00r = splat2(u[0]); g.c00in = splat2(-u[1]); g.c00ip = splat2(u[1]);
    g.c01r = splat2(u[2]); g.c01in = splat2(-u[3]); g.c01ip = splat2(u[3]);
    g.c10r = splat2(u[4]); g.c10in = splat2(-u[5]); g.c10ip = splat2(u[5]);
    g.c11r = splat2(u[6]); g.c11in = splat2(-u[7]); g.c11ip = splat2(u[7]);
    return g;
}
__device__ __forceinline__ void bf(const CGate& g, ull& ar, ull& ai, ull& br, ull& bi) {
    ull nar = fma2(g.c00r, ar, fma2(g.c00in, ai, fma2(g.c01r, br, mul2(g.c01in, bi))));
    ull nai = fma2(g.c00r, ai, fma2(g.c00ip, ar, fma2(g.c01r, bi, mul2(g.c01ip, br))));
    ull nbr = fma2(g.c10r, ar, fma2(g.c10in, ai, fma2(g.c11r, br, mul2(g.c11in, bi))));
    ull nbi = fma2(g.c10r, ai, fma2(g.c10ip, ar, fma2(g.c11r, bi, mul2(g.c11ip, br))));
    ar = nar; ai = nai; br = nbr; bi = nbi;
}
// "mine + partner" half-butterfly: new_m = cm*mine + cp*partner (complex)
struct PGate { ull cmr, cmin, cmip, cpr, cpin, cpip; };
__device__ __forceinline__ PGate make_pgate(float cmr, float cmi, float cpr, float cpi) {
    PGate g;
    g.cmr = splat2(cmr); g.cmin = splat2(-cmi); g.cmip = splat2(cmi);
    g.cpr = splat2(cpr); g.cpin = splat2(-cpi); g.cpip = splat2(cpi);
    return g;
}
__device__ __forceinline__ void bfp(const PGate& g, ull& mr, ull& mi, ull pr, ull pi) {
    ull nr = fma2(g.cmr, mr, fma2(g.cmin, mi, fma2(g.cpr, pr, mul2(g.cpin, pi))));
    ull ni = fma2(g.cmr, mi, fma2(g.cmip, mr, fma2(g.cpr, pi, mul2(g.cpip, pr))));
    mr = nr; mi = ni;
}
// real CRY butterfly: a' = c a - s b ; b' = s a + c b
__device__ __forceinline__ void cry_bf(ull CC, ull CSn, ull CSp, ull& ar, ull& ai, ull& br, ull& bi) {
    ull nar = fma2(CC, ar, mul2(CSn, br));
    ull nai = fma2(CC, ai, mul2(CSn, bi));
    ull nbr = fma2(CC, br, mul2(CSp, ar));
    ull nbi = fma2(CC, bi, mul2(CSp, ai));
    ar = nar; ai = nai; br = nbr; bi = nbi;
}

// ---------------- kernel 1: encoded = x @ enc_w.T + enc_b ----------------
__global__ void k_encode(const float* __restrict__ x,
                         const float* __restrict__ enc_w,
                         const float* __restrict__ enc_b) {
    __shared__ float w_s[NQ * IN_SIZE];
    int tid = threadIdx.x;
    for (int i = tid; i < NQ * IN_SIZE; i += 256) w_s[i] = enc_w[i];
    __syncthreads();
    int warp = tid >> 5, lane = tid & 31;
    int row = blockIdx.x * 8 + warp;
    const float* xr = x + row * IN_SIZE;
    float acc[NQ];
#pragma unroll
    for (int q = 0; q < NQ; ++q) acc[q] = 0.f;
    for (int k = lane; k < IN_SIZE; k += 32) {
        float xv = xr[k];
#pragma unroll
        for (int q = 0; q < NQ; ++q) acc[q] += xv * w_s[q * IN_SIZE + k];
    }
#pragma unroll
    for (int q = 0; q < NQ; ++q) {
#pragma unroll
        for (int o = 16; o > 0; o >>= 1)
            acc[q] += __shfl_xor_sync(0xffffffffu, acc[q], o);
    }
    if (lane == 0) {
#pragma unroll
        for (int q = 0; q < NQ; ++q)
            g_encoded[row * NQ + q] = acc[q] + enc_b[q];
    }
}

// ---------------- kernel 2: BN1 stats + gate precompute ----------------
struct C2 { float r, i; };
__device__ __forceinline__ C2 cmul(C2 a, C2 b) { C2 c; c.r = a.r*b.r - a.i*b.i; c.i = a.r*b.i + a.i*b.r; return c; }
__device__ __forceinline__ C2 cadd(C2 a, C2 b) { C2 c; c.r = a.r + b.r; c.i = a.i + b.i; return c; }
__device__ void mm2(const C2* A, const C2* Bm, C2* O) {
    O[0] = cadd(cmul(A[0], Bm[0]), cmul(A[1], Bm[2]));
    O[1] = cadd(cmul(A[0], Bm[1]), cmul(A[1], Bm[3]));
    O[2] = cadd(cmul(A[2], Bm[0]), cmul(A[3], Bm[2]));
    O[3] = cadd(cmul(A[2], Bm[1]), cmul(A[3], Bm[3]));
}

__global__ void k_prep(const float* __restrict__ rot_params,
                       const float* __restrict__ ent_params,
                       const float* __restrict__ bn1_gamma,
                       const float* __restrict__ bn1_beta) {
    int tid = threadIdx.x;
    if (blockIdx.x < NQ) {
        int f = blockIdx.x;
        float s = 0.f, s2 = 0.f;
        for (int r = tid; r < B; r += 256) {
            float v = g_encoded[r * NQ + f];
            s += v; s2 += v * v;
        }
#pragma unroll
        for (int o = 16; o > 0; o >>= 1) {
            s  += __shfl_xor_sync(0xffffffffu, s, o);
            s2 += __shfl_xor_sync(0xffffffffu, s2, o);
        }
        __shared__ float rs[8], rs2[8];
        int w = tid >> 5, lane = tid & 31;
        if (lane == 0) { rs[w] = s; rs2[w] = s2; }
        __syncthreads();
        if (tid == 0) {
            float S = 0.f, S2 = 0.f;
            for (int i = 0; i < 8; ++i) { S += rs[i]; S2 += rs2[i]; }
            float mean = S / (float)B;
            float var = S2 / (float)B - mean * mean;
            float sc = bn1_gamma[f] * rsqrtf(var + BN_EPS);
            g_bn1_sc[f] = sc;
            g_bn1_sh[f] = bn1_beta[f] - mean * sc;
        }
    } else {
        if (tid < DEPTH * NQ) {
            int l = tid / NQ, q = tid % NQ;
            float a = rot_params[(l * NQ + q) * 3 + 0];
            float b = rot_params[(l * NQ + q) * 3 + 1];
            float g = rot_params[(l * NQ + q) * 3 + 2];
            float cx = cosf(0.5f*a), sx = sinf(0.5f*a);
            float cy = cosf(0.5f*b), sy = sinf(0.5f*b);
            float cg = cosf(0.5f*g), sg = sinf(0.5f*g);
            C2 Rx[4] = { {cx,0.f},{0.f,-sx},{0.f,-sx},{cx,0.f} };
            C2 Ry[4] = { {cy,0.f},{-sy,0.f},{sy,0.f},{cy,0.f} };
            C2 Rz[4] = { {cg,-sg},{0.f,0.f},{0.f,0.f},{cg,sg} };
            C2 T[4], U[4];
            mm2(Ry, Rx, T);
            mm2(Rz, T, U);
            float* o = &g_gates[tid * 8];
#pragma unroll
            for (int e = 0; e < 4; ++e) { o[e*2] = U[e].r; o[e*2+1] = U[e].i; }
        }
        if (tid >= 64 && tid < 64 + DEPTH * (NQ - 1)) {
            int t = tid - 64;
            float th = ent_params[t];
            g_cry[t*2]   = cosf(0.5f * th);
            g_cry[t*2+1] = sinf(0.5f * th);
        }
    }
}

// ---------------- kernel 3: register-resident quantum simulator ----------------
// thread t: amp bits [11:9]=t[7:5], [8:4]=t[4:0], [3:0]=loc. SoA f32x2 over loc bit 0.
__global__ __launch_bounds__(256) void k_quantum(const float* __restrict__ dec_w,
                                                 const float* __restrict__ dec_b,
                                                 float* __restrict__ out) {
    __shared__ ull sb[256 * 17];              // exchange buffer (pad 17 vs bank conflicts)
    __shared__ float sg[DEPTH * NQ * 8];
    __shared__ float scry[DEPTH * (NQ - 1) * 2];
    __shared__ float hq0[NQ], hq1[NQ];
    __shared__ float wsum[8][NQ];
    __shared__ float probs_s[NQ];

    int t = threadIdx.x;
    int lane = t & 31;
    int sample = blockIdx.x;

    for (int i = t; i < DEPTH * NQ * 8; i += 256) sg[i] = g_gates[i];
    if (t < DEPTH * (NQ - 1) * 2) scry[t] = g_cry[t];
    if (t < NQ) {
        float e = g_encoded[sample * NQ + t];
        hq0[t] = tanhf(g_bn1_sc[t] * e + g_bn1_sh[t]);
    }
    __syncthreads();
    if (t == 0) {
        float ss = 0.f;
#pragma unroll
        for (int q = 0; q < NQ; ++q) ss += hq0[q] * hq0[q];
        float nrm = sqrtf(ss);
#pragma unroll
        for (int q = 0; q < NQ; ++q) {
            float h = hq0[q];
            float a = (nrm > 0.f) ? h / fmaxf(nrm, 1e-30f) : h;
            float amp = fminf(fabsf(a), 1.0f);
            float ch = sqrtf(fmaxf(1.0f - amp * amp, 0.0f));
            hq0[q] = ch;
            hq1[q] = (a < 0.f) ? -amp : amp;
        }
    }
    __syncthreads();

    // initial product state (real)
    float ft = 1.f;
#pragma unroll
    for (int m = 4; m < 12; ++m) {
        int q = 11 - m;
        ft *= ((t >> (m - 4)) & 1) ? hq1[q] : hq0[q];
    }
    ull vr[8], vi[8];
#pragma unroll
    for (int k = 0; k < 8; ++k) {
        float lo = ft, hi = ft;
        int loc0 = 2 * k, loc1 = 2 * k + 1;
#pragma unroll
        for (int m = 0; m < 4; ++m) {
            int q = 11 - m;
            lo *= ((loc0 >> m) & 1) ? hq1[q] : hq0[q];
            hi *= ((loc1 >> m) & 1) ? hq1[q] : hq0[q];
        }
        vr[k] = pack2(lo, hi);
        vi[k] = pack2(0.f, 0.f);
    }

    for (int l = 0; l < DEPTH; ++l) {
        const float* G = sg + l * NQ * 8;

        // ---- 1q gates (commute; grouped by comm tier) ----
        // m=0 (q=11): intra-packed
        {
            const float* u = G + 11 * 8;
            ull C1r = pack2(u[0], u[6]), C1in = pack2(-u[1], -u[7]), C1ip = pack2(u[1], u[7]);
            ull C2r = pack2(u[2], u[4]), C2in = pack2(-u[3], -u[5]), C2ip = pack2(u[3], u[5]);
#pragma unroll
            for (int k = 0; k < 8; ++k) {
                ull Pr = vr[k], Pi = vi[k], Qr = swap2(Pr), Qi = swap2(Pi);
                vr[k] = fma2(C1r, Pr, fma2(C1in, Pi, fma2(C2r, Qr, mul2(C2in, Qi))));
                vi[k] = fma2(C1r, Pi, fma2(C1ip, Pr, fma2(C2r, Qi, mul2(C2ip, Qr))));
            }
        }
        // m=1..3: register pairs across k
#pragma unroll
        for (int m = 1; m < 4; ++m) {
            CGate g = make_cgate(G + (11 - m) * 8);
            int kb = 1 << (m - 1);
#pragma unroll
            for (int k0 = 0; k0 < 8; ++k0)
                if (!(k0 & kb)) bf(g, vr[k0], vi[k0], vr[k0 | kb], vi[k0 | kb]);
        }
        // m=4..8: warp shuffle
#pragma unroll
        for (int m = 4; m < 9; ++m) {
            const float* u = G + (11 - m) * 8;
            int lb = m - 4;
            int bit = (lane >> lb) & 1;
            PGate g = make_pgate(bit ? u[6] : u[0], bit ? u[7] : u[1],
                                 bit ? u[4] : u[2], bit ? u[5] : u[3]);
#pragma unroll
            for (int k = 0; k < 8; ++k) {
                ull pr = __shfl_xor_sync(0xffffffffu, vr[k], 1 << lb);
                ull pi = __shfl_xor_sync(0xffffffffu, vi[k], 1 << lb);
                bfp(g, vr[k], vi[k], pr, pi);
            }
        }
        // m=9..11: smem exchange
        for (int m = 9; m < 12; ++m) {
            const float* u = G + (11 - m) * 8;
            int tb = m - 4;
            int X = 1 << tb;
            int bit = (t >> tb) & 1;
            PGate g = make_pgate(bit ? u[6] : u[0], bit ? u[7] : u[1],
                                 bit ? u[4] : u[2], bit ? u[5] : u[3]);
#pragma unroll
            for (int k = 0; k < 8; ++k) { sb[t * 17 + k] = vr[k]; sb[t * 17 + 8 + k] = vi[k]; }
            __syncthreads();
            int p = t ^ X;
#pragma unroll
            for (int k = 0; k < 8; ++k) {
                ull pr = sb[p * 17 + k], pi = sb[p * 17 + 8 + k];
                bfp(g, vr[k], vi[k], pr, pi);
            }
            __syncthreads();
        }

        // ---- CRY chain j=0..10, target bit mt=10-j, control bit mt+1 ----
        const float* E = scry + l * (NQ - 1) * 2;
        // j=0 (mt=10, ctrl bit 11 = t bit7) and j=1 (mt=9, ctrl bit 10 = t bit6): smem
#pragma unroll
        for (int j = 0; j < 2; ++j) {
            int mt = 10 - j;
            float c = E[j * 2], s = E[j * 2 + 1];
            int tb = mt - 4;                 // 6, 5
            int X = 1 << tb;
            int part = (t >> (tb + 1)) & 1;  // control bit
            int bit = (t >> tb) & 1;
            ull CC = splat2(c), CP = splat2(bit ? s : -s);
            if (part) {
#pragma unroll
                for (int k = 0; k < 8; ++k) { sb[t * 17 + k] = vr[k]; sb[t * 17 + 8 + k] = vi[k]; }
            }
            __syncthreads();
            if (part) {
                int p = t ^ X;
#pragma unroll
                for (int k = 0; k < 8; ++k) {
                    ull pr = sb[p * 17 + k], pi = sb[p * 17 + 8 + k];
                    vr[k] = fma2(CC, vr[k], mul2(CP, pr));
                    vi[k] = fma2(CC, vi[k], mul2(CP, pi));
                }
            }
            __syncthreads();
        }
        // j=2..6 (mt=8..4): shuffle
#pragma unroll
        for (int j = 2; j < 7; ++j) {
            int mt = 10 - j;
            float c = E[j * 2], s = E[j * 2 + 1];
            int lb = mt - 4;
            int part = (mt == 8) ? ((t >> 5) & 1) : ((lane >> (lb + 1)) & 1);
            int bit = (lane >> lb) & 1;
            ull CC = splat2(c), CP = splat2(bit ? s : -s);
#pragma unroll
            for (int k = 0; k < 8; ++k) {
                ull pr = __shfl_xor_sync(0xffffffffu, vr[k], 1 << lb);
                ull pi = __shfl_xor_sync(0xffffffffu, vi[k], 1 << lb);
                if (part) {
                    vr[k] = fma2(CC, vr[k], mul2(CP, pr));
                    vi[k] = fma2(CC, vi[k], mul2(CP, pi));
                }
            }
        }
        // j=7 (mt=3, ctrl = amp bit4 = lane bit0): register pairs (k0, k0+4)
        {
            float c = E[14], s = E[15];
            if (lane & 1) {
                ull CC = splat2(c), CSn = splat2(-s), CSp = splat2(s);
#pragma unroll
                for (int k0 = 0; k0 < 4; ++k0)
                    cry_bf(CC, CSn, CSp, vr[k0], vi[k0], vr[k0 + 4], vi[k0 + 4]);
            }
        }
        // j=8 (mt=2, ctrl = k bit2): pairs (4,6),(5,7)
        {
            float c = E[16], s = E[17];
            ull CC = splat2(c), CSn = splat2(-s), CSp = splat2(s);
            cry_bf(CC, CSn, CSp, vr[4], vi[4], vr[6], vi[6]);
            cry_bf(CC, CSn, CSp, vr[5], vi[5], vr[7], vi[7]);
        }
        // j=9 (mt=1, ctrl = k bit1): pairs (2,3),(6,7)
        {
            float c = E[18], s = E[19];
            ull CC = splat2(c), CSn = splat2(-s), CSp = splat2(s);
            cry_bf(CC, CSn, CSp, vr[2], vi[2], vr[3], vi[3]);
            cry_bf(CC, CSn, CSp, vr[6], vi[6], vr[7], vi[7]);
        }
        // j=10 (mt=0, ctrl = k bit0): intra-packed, odd k only
        {
            float c = E[20], s = E[21];
            ull CC = splat2(c), SS = pack2(-s, s);
#pragma unroll
            for (int k = 1; k < 8; k += 2) {
                ull Pr = vr[k], Pi = vi[k];
                vr[k] = fma2(CC, Pr, mul2(SS, swap2(Pr)));
                vi[k] = fma2(CC, Pi, mul2(SS, swap2(Pi)));
            }
        }
    }

    // ---- probs per qubit ----
    float acc[NQ];
    {
        float tot = 0.f, sm0 = 0.f, sm1 = 0.f, sm2 = 0.f, sm3 = 0.f;
#pragma unroll
        for (int k = 0; k < 8; ++k) {
            ull p2 = fma2(vr[k], vr[k], mul2(vi[k], vi[k]));
            float plo, phi;
            unpack2(p2, plo, phi);
            float pk = plo + phi;
            tot += pk;
            sm0 += phi;
            if (k & 1) sm1 += pk;
            if (k & 2) sm2 += pk;
            if (k & 4) sm3 += pk;
        }
        acc[11] = sm0; acc[10] = sm1; acc[9] = sm2; acc[8] = sm3;
#pragma unroll
        for (int m = 4; m < 12; ++m)
            acc[11 - m] = ((t >> (m - 4)) & 1) ? tot : 0.f;
    }
#pragma unroll
    for (int q = 0; q < NQ; ++q) {
#pragma unroll
        for (int o = 16; o > 0; o >>= 1)
            acc[q] += __shfl_xor_sync(0xffffffffu, acc[q], o);
    }
    int w = t >> 5;
    if (lane == 0) {
#pragma unroll
        for (int q = 0; q < NQ; ++q) wsum[w][q] = acc[q];
    }
    __syncthreads();
    if (t < NQ) {
        float s = 0.f;
#pragma unroll
        for (int ww = 0; ww < 8; ++ww) s += wsum[ww][t];
        probs_s[t] = s;
    }
    __syncthreads();

    // decode (pre-BN2)
    {
        float o = dec_b[t];
#pragma unroll
        for (int q = 0; q < NQ; ++q) o += probs_s[q] * dec_w[t * NQ + q];
        out[sample * OUT_SIZE + t] = o;
    }
}

// ---------------- BN2: coalesced two-stage stats ----------------
__global__ void k_bn2_part(const float* __restrict__ out) {
    int t = threadIdx.x;
    int base = blockIdx.x * 64;
    float s = 0.f, s2 = 0.f;
    for (int r = 0; r < 64; ++r) {
        float v = out[(base + r) * OUT_SIZE + t];
        s += v; s2 += v * v;
    }
    g_p1[blockIdx.x * OUT_SIZE + t] = s;
    g_p2[blockIdx.x * OUT_SIZE + t] = s2;
}

__global__ void k_bn2_fin(const float* __restrict__ bn2_gamma,
                          const float* __restrict__ bn2_beta) {
    int t = threadIdx.x;
    float S = 0.f, S2 = 0.f;
#pragma unroll
    for (int i = 0; i < 64; ++i) { S += g_p1[i * OUT_SIZE + t]; S2 += g_p2[i * OUT_SIZE + t]; }
    float mean = S / (float)B;
    float var = S2 / (float)B - mean * mean;
    float sc = bn2_gamma[t] * rsqrtf(var + BN_EPS);
    g_bn2_sc[t] = sc;
    g_bn2_sh[t] = bn2_beta[t] - mean * sc;
}

__global__ void k_bn2_apply(float* __restrict__ out) {
    int i = blockIdx.x * 256 + threadIdx.x;
    int f = i & (OUT_SIZE - 1);
    out[i] = g_bn2_sc[f] * out[i] + g_bn2_sh[f];
}

// ---------------- launcher ----------------
extern "C" void kernel_launch(void* const* d_in, const int* in_sizes, int n_in,
                              void* d_out, int out_size) {
    const float* x          = (const float*)d_in[0];
    const float* enc_w      = (const float*)d_in[1];
    const float* enc_b      = (const float*)d_in[2];
    const float* rot_params = (const float*)d_in[3];
    const float* ent_params = (const float*)d_in[4];
    const float* dec_w      = (const float*)d_in[5];
    const float* dec_b      = (const float*)d_in[6];
    const float* bn1_gamma  = (const float*)d_in[7];
    const float* bn1_beta   = (const float*)d_in[8];
    const float* bn2_gamma  = (const float*)d_in[9];
    const float* bn2_beta   = (const float*)d_in[10];
    float* out = (float*)d_out;

    k_encode<<<B / 8, 256>>>(x, enc_w, enc_b);
    k_prep<<<NQ + 1, 256>>>(rot_params, ent_params, bn1_gamma, bn1_beta);
    k_quantum<<<B, 256>>>(dec_w, dec_b, out);
    k_bn2_part<<<64, 256>>>(out);
    k_bn2_fin<<<1, 256>>>(bn2_gamma, bn2_beta);
    k_bn2_apply<<<(B * OUT_SIZE) / 256, 256>>>(out);
}